// round 13
// baseline (speedup 1.0000x reference)
#include <cuda_runtime.h>

#define N_NODES   8192
#define T_TYPES   4
#define E_EDGES   131072
#define E_TOTAL   (T_TYPES * E_EDGES)   // 524288
#define H_HEADS   4
#define D_DIM     32
#define NEG_SLOPE 0.2f
#define WSTR      34                    // D_DIM + 2

// Lossy 4-bit counting table: 2^23 fields packed 8/word = 4 MiB
#define LSY_WORDS (1u << 20)
// Exact dup hash (true dups + ~6% lossy false positives, ~32K keys)
#define DUP_BITS  17
#define DUP_SIZE  (1u << DUP_BITS)
#define DUP_MASK  (DUP_SIZE - 1u)

#define GRID1       512                 // 4 edges/thread; (256,4) launch bounds
                                        // → <=64 regs → all 512 blocks resident
#define FIN_BLOCKS   32                 // 8192/256
#define CLR_L_BLOCKS 64
#define CLR_D_BLOCKS 32
#define K2_BLOCKS   (FIN_BLOCKS + CLR_L_BLOCKS + CLR_D_BLOCKS)  // 128

// Scratch — zero-init at module load; self-cleaned every call (K2).
__device__ unsigned int g_lsy[LSY_WORDS];
__device__ unsigned int g_dkey[DUP_SIZE];   // 0=empty else key+1
__device__ unsigned int g_dcnt[DUP_SIZE];   // packed per-type byte counts
__device__ float4 g_acc[N_NODES * 2];       // [d0,n0,d1,n1][d2,n2,d3,n3]
__device__ float4 g_embT[T_TYPES];          // embterm[t] over 4 heads
__device__ float  g_part[32];               // score partial sums
__device__ unsigned int g_barA;             // grid barrier counter (reset in K2)

__device__ __forceinline__ unsigned int field_of(unsigned int key) {
    return (key * 0x9E3779B1u) >> 9;        // 23-bit field index
}

// L2-coherent load — required for data mutated within this kernel launch
// (the R10 lesson: __ldg on such data is UB and silently corrupts).
__device__ __forceinline__ unsigned int ld_cg_u32(const unsigned int* p) {
    unsigned int v;
    asm volatile("ld.global.cg.u32 %0, [%1];" : "=r"(v) : "l"(p) : "memory");
    return v;
}
__device__ __forceinline__ float4 ld_cg_f4(const float4* p) {
    float4 v;
    asm volatile("ld.global.cg.v4.f32 {%0,%1,%2,%3}, [%4];"
                 : "=f"(v.x), "=f"(v.y), "=f"(v.z), "=f"(v.w) : "l"(p) : "memory");
    return v;
}

__device__ __forceinline__ float group_ex(
        unsigned int c, float si, float sj,
        float ws, float wt, float et0, float et1, float et2, float et3) {
    float c0 = (float)( c        & 0xFFu);
    float c1 = (float)((c >> 8 ) & 0xFFu);
    float c2 = (float)((c >> 16) & 0xFFu);
    float c3 = (float)((c >> 24) & 0xFFu);
    float a = (si * ws + sj * wt) * (c0 + c1 + c2 + c3)
            + c0 * et0 + c1 * et1 + c2 * et2 + c3 * et3;
    return __expf(fmaxf(a, NEG_SLOPE * a)) - 1.f;
}

// ---------------------------------------------------------------------------
// K1: [count + prep] -> threadfence -> grid barrier (all blocks resident)
//     -> [resolve: singleton fast path OR inline telescoping delta].
// Edges loaded once; stay in registers across the barrier.
// ---------------------------------------------------------------------------
__global__ void __launch_bounds__(256, 4) k_main(
        const int*   __restrict__ ei,
        const float* __restrict__ scores,
        const float* __restrict__ emb,
        const float* __restrict__ W) {
    const int bid = blockIdx.x, tid = threadIdx.x;
    const int gtid = bid * 256 + tid;
    const int base = gtid * 4;              // 4 contiguous edges, same type t
    const int t = base >> 17, e = base & (E_EDGES - 1);

    int4 s4 = __ldg((const int4*)(ei + (t * 2    ) * E_EDGES + e));
    int4 t4 = __ldg((const int4*)(ei + (t * 2 + 1) * E_EDGES + e));

    unsigned int key[4], f[4];
    key[0] = ((unsigned)s4.x << 13) | (unsigned)t4.x;  f[0] = field_of(key[0]);
    key[1] = ((unsigned)s4.y << 13) | (unsigned)t4.y;  f[1] = field_of(key[1]);
    key[2] = ((unsigned)s4.z << 13) | (unsigned)t4.z;  f[2] = field_of(key[2]);
    key[3] = ((unsigned)s4.w << 13) | (unsigned)t4.w;  f[3] = field_of(key[3]);

    #pragma unroll
    for (int k = 0; k < 4; k++)
        asm volatile("red.global.add.u32 [%0], %1;"
                     :: "l"(&g_lsy[f[k] >> 3]),
                        "r"(1u << ((f[k] & 7u) * 4u)) : "memory");

    // distributed prep, overlapped with count drain
    if (bid < 32) {
        __shared__ float red[256];
        red[tid] = __ldg(scores + bid * 256 + tid);
        __syncthreads();
        for (int o = 128; o > 0; o >>= 1) {
            if (tid < o) red[tid] += red[tid + o];
            __syncthreads();
        }
        if (tid == 0) g_part[bid] = red[0];
    } else if (bid == 32 && tid < T_TYPES) {
        float r[H_HEADS];
        #pragma unroll
        for (int h = 0; h < H_HEADS; h++) {
            float a = 0.f;
            #pragma unroll
            for (int d = 0; d < D_DIM; d++)
                a += __ldg(emb + tid * D_DIM + d) * __ldg(W + h * WSTR + 1 + d);
            r[h] = a;
        }
        g_embT[tid] = make_float4(r[0], r[1], r[2], r[3]);
    }

    // publish this thread's REDs before the barrier arrive (R11-proven)
    __threadfence();

    // ---- grid barrier: all 512 blocks co-resident → deadlock-free ----
    __syncthreads();
    if (tid == 0) {
        asm volatile("red.release.gpu.global.add.u32 [%0], %1;"
                     :: "l"(&g_barA), "r"(1u) : "memory");
        unsigned int v;
        do {
            asm volatile("ld.acquire.gpu.global.u32 %0, [%1];"
                         : "=r"(v) : "l"(&g_barA) : "memory");
        } while (v < (unsigned)GRID1);
    }
    __syncthreads();

    // ---- resolve (edges still in registers); coherent .cg reads ----
    unsigned int w[4];
    #pragma unroll
    for (int k = 0; k < 4; k++) w[k] = ld_cg_u32(&g_lsy[f[k] >> 3]);

    float4 embT = ld_cg_f4(&g_embT[t]);
    float ws0 = __ldg(W + 0 * WSTR), wt0 = __ldg(W + 0 * WSTR + 33);
    float ws1 = __ldg(W + 1 * WSTR), wt1 = __ldg(W + 1 * WSTR + 33);
    float ws2 = __ldg(W + 2 * WSTR), wt2 = __ldg(W + 2 * WSTR + 33);
    float ws3 = __ldg(W + 3 * WSTR), wt3 = __ldg(W + 3 * WSTR + 33);

    #pragma unroll
    for (int k = 0; k < 4; k++) {
        unsigned int cnt = (w[k] >> ((f[k] & 7u) * 4u)) & 15u;
        unsigned int src = key[k] >> 13, tgt = key[k] & 8191u;
        float si = __ldg(scores + src);
        float sj = __ldg(scores + tgt);
        float ex0, ex1, ex2, ex3;

        if (cnt == 1u) {                    // exact singleton (~94%)
            float a0 = si * ws0 + sj * wt0 + embT.x;
            float a1 = si * ws1 + sj * wt1 + embT.y;
            float a2 = si * ws2 + sj * wt2 + embT.z;
            float a3 = si * ws3 + sj * wt3 + embT.w;
            ex0 = __expf(fmaxf(a0, NEG_SLOPE * a0)) - 1.f;
            ex1 = __expf(fmaxf(a1, NEG_SLOPE * a1)) - 1.f;
            ex2 = __expf(fmaxf(a2, NEG_SLOPE * a2)) - 1.f;
            ex3 = __expf(fmaxf(a3, NEG_SLOPE * a3)) - 1.f;
        } else {                            // dup/collision: telescoping delta
            unsigned int hh = key[k] * 0x85EBCA6Bu;
            hh = (hh ^ (hh >> 16)) & DUP_MASK;
            while (true) {
                unsigned int o = atomicCAS(&g_dkey[hh], 0u, key[k] + 1u);
                if (o == 0u || o == key[k] + 1u) break;
                hh = (hh + 1u) & DUP_MASK;
            }
            unsigned int inc   = 1u << (t * 8);
            unsigned int c_old = atomicAdd(&g_dcnt[hh], inc);
            unsigned int c_new = c_old + inc;
            float4 E0 = ld_cg_f4(&g_embT[0]);
            float4 E1 = ld_cg_f4(&g_embT[1]);
            float4 E2 = ld_cg_f4(&g_embT[2]);
            float4 E3 = ld_cg_f4(&g_embT[3]);
            ex0 = group_ex(c_new, si, sj, ws0, wt0, E0.x, E1.x, E2.x, E3.x)
                - group_ex(c_old, si, sj, ws0, wt0, E0.x, E1.x, E2.x, E3.x);
            ex1 = group_ex(c_new, si, sj, ws1, wt1, E0.y, E1.y, E2.y, E3.y)
                - group_ex(c_old, si, sj, ws1, wt1, E0.y, E1.y, E2.y, E3.y);
            ex2 = group_ex(c_new, si, sj, ws2, wt2, E0.z, E1.z, E2.z, E3.z)
                - group_ex(c_old, si, sj, ws2, wt2, E0.z, E1.z, E2.z, E3.z);
            ex3 = group_ex(c_new, si, sj, ws3, wt3, E0.w, E1.w, E2.w, E3.w)
                - group_ex(c_old, si, sj, ws3, wt3, E0.w, E1.w, E2.w, E3.w);
        }

        float4* dst = &g_acc[src * 2];
        asm volatile("red.global.add.v4.f32 [%0], {%1,%2,%3,%4};"
                     :: "l"(dst), "f"(ex0), "f"(ex0 * sj),
                        "f"(ex1), "f"(ex1 * sj) : "memory");
        asm volatile("red.global.add.v4.f32 [%0], {%1,%2,%3,%4};"
                     :: "l"(dst + 1), "f"(ex2), "f"(ex2 * sj),
                        "f"(ex3), "f"(ex3 * sj) : "memory");
    }
}

// ---------------------------------------------------------------------------
// K2: blocks [0,32) finalize + reset g_acc; [32,96) clear lossy table
//     (+ reset g_barA); [96,128) clear dup hash. No internal ordering needed.
// ---------------------------------------------------------------------------
__global__ void __launch_bounds__(256) k_final(float* __restrict__ out) {
    const int bid = blockIdx.x, tid = threadIdx.x;
    uint4 z4 = make_uint4(0u, 0u, 0u, 0u);

    if (bid < FIN_BLOCKS) {
        float st = 0.f;
        #pragma unroll
        for (int k = 0; k < 32; k++) st += g_part[k];   // deterministic order
        int i = bid * 256 + tid;
        float4 a0 = g_acc[i * 2];
        float4 a1 = g_acc[i * 2 + 1];
        out[i] = 0.25f * ((st + a0.y) / (8192.f + a0.x)
                        + (st + a0.w) / (8192.f + a0.z)
                        + (st + a1.y) / (8192.f + a1.x)
                        + (st + a1.w) / (8192.f + a1.z));
        g_acc[i * 2]     = make_float4(0.f, 0.f, 0.f, 0.f);
        g_acc[i * 2 + 1] = make_float4(0.f, 0.f, 0.f, 0.f);
    } else if (bid < FIN_BLOCKS + CLR_L_BLOCKS) {
        if (bid == FIN_BLOCKS && tid == 0) g_barA = 0u;  // reset grid barrier
        uint4* l4 = (uint4*)g_lsy;                       // 2^18 uint4
        unsigned int b = (unsigned)(bid - FIN_BLOCKS) * 256 + tid;
        #pragma unroll
        for (int k = 0; k < 16; k++)
            l4[b + k * (CLR_L_BLOCKS * 256)] = z4;
    } else {
        uint4* k4 = (uint4*)g_dkey;                      // 2^15 uint4
        uint4* c4 = (uint4*)g_dcnt;
        unsigned int b = (unsigned)(bid - FIN_BLOCKS - CLR_L_BLOCKS) * 256 + tid;
        #pragma unroll
        for (int k = 0; k < 4; k++) {
            k4[b + k * (CLR_D_BLOCKS * 256)] = z4;
            c4[b + k * (CLR_D_BLOCKS * 256)] = z4;
        }
    }
}

// ---------------------------------------------------------------------------
extern "C" void kernel_launch(void* const* d_in, const int* in_sizes, int n_in,
                              void* d_out, int out_size) {
    const float* scores = (const float*)d_in[0];   // (N, 1)
    const float* emb    = (const float*)d_in[1];   // (T, D)
    const int*   ei     = (const int*)  d_in[2];   // (T, 2, E)
    const float* W      = (const float*)d_in[3];   // (H, D+2, 1)
    float*       out    = (float*)d_out;           // (N, 1)

    k_main <<<GRID1,     256>>>(ei, scores, emb, W);
    k_final<<<K2_BLOCKS, 256>>>(out);
}

// round 14
// speedup vs baseline: 1.4269x; 1.4269x over previous
#include <cuda_runtime.h>

#define N_NODES   8192
#define T_TYPES   4
#define E_EDGES   131072
#define E_TOTAL   (T_TYPES * E_EDGES)   // 524288
#define H_HEADS   4
#define D_DIM     32
#define NEG_SLOPE 0.2f
#define WSTR      34                    // D_DIM + 2

// Lossy 4-bit counting table: 2^23 fields packed 8/word = 4 MiB
#define LSY_WORDS (1u << 20)
// Exact dup hash (true dups + ~6% lossy false positives, ~32K keys)
#define DUP_BITS  17
#define DUP_SIZE  (1u << DUP_BITS)
#define DUP_MASK  (DUP_SIZE - 1u)

#define EDGE_BLOCKS (E_TOTAL / 512)     // 1024 (2 edges/thread)
#define FIN_BLOCKS   32                 // 8192/256
#define CLR_L_BLOCKS 128                // 4MB: 128*256*8 uint4
#define K3_BLOCKS   (FIN_BLOCKS + CLR_L_BLOCKS)  // 160

// Scratch — zero-init at module load; self-cleaned every call.
__device__ unsigned int g_lsy[LSY_WORDS];
__device__ unsigned int g_dkey[DUP_SIZE];   // 0=empty else key+1 (cleared in k_count)
__device__ unsigned int g_dcnt[DUP_SIZE];   // packed per-type byte counts
__device__ float4 g_acc[N_NODES * 2];       // [d0,n0,d1,n1][d2,n2,d3,n3]
__device__ float4 g_embT[T_TYPES];          // embterm[t] over 4 heads
__device__ float  g_part[32];               // score partial sums

__device__ __forceinline__ unsigned int field_of(unsigned int key) {
    return (key * 0x9E3779B1u) >> 9;        // 23-bit field index
}

__device__ __forceinline__ float group_ex(
        unsigned int c, float si, float sj,
        float ws, float wt, float et0, float et1, float et2, float et3) {
    float c0 = (float)( c        & 0xFFu);
    float c1 = (float)((c >> 8 ) & 0xFFu);
    float c2 = (float)((c >> 16) & 0xFFu);
    float c3 = (float)((c >> 24) & 0xFFu);
    float a = (si * ws + sj * wt) * (c0 + c1 + c2 + c3)
            + c0 * et0 + c1 * et1 + c2 * et2 + c3 * et3;
    return __expf(fmaxf(a, NEG_SLOPE * a)) - 1.f;
}

// ---------------------------------------------------------------------------
// K1: lossy counting (fire-and-forget REDs, 2 edges/thread) + prep +
// dup-hash clear folded into the latency bubbles. No sync.
// ---------------------------------------------------------------------------
__global__ void __launch_bounds__(256) k_count(
        const int*   __restrict__ ei,
        const float* __restrict__ scores,
        const float* __restrict__ emb,
        const float* __restrict__ W) {
    const int bid = blockIdx.x, tid = threadIdx.x;
    const int gtid = bid * 256 + tid;
    const int base = gtid * 2;              // 2 contiguous edges, same type t
    const int t = base >> 17, e = base & (E_EDGES - 1);

    int2 s2 = __ldg((const int2*)(ei + (t * 2    ) * E_EDGES + e));
    int2 t2 = __ldg((const int2*)(ei + (t * 2 + 1) * E_EDGES + e));

    unsigned int f0 = field_of(((unsigned)s2.x << 13) | (unsigned)t2.x);
    unsigned int f1 = field_of(((unsigned)s2.y << 13) | (unsigned)t2.y);
    asm volatile("red.global.add.u32 [%0], %1;"
                 :: "l"(&g_lsy[f0 >> 3]), "r"(1u << ((f0 & 7u) * 4u)) : "memory");
    asm volatile("red.global.add.u32 [%0], %1;"
                 :: "l"(&g_lsy[f1 >> 3]), "r"(1u << ((f1 & 7u) * 4u)) : "memory");

    // clear dup hash for this call's k_edges (1 MB over 1024 blocks × 64 thr)
    if (tid < 64) {
        unsigned int idx = (unsigned)bid * 64 + tid;     // 65536 uint4 total
        uint4 z4 = make_uint4(0u, 0u, 0u, 0u);
        if (idx < 32768) ((uint4*)g_dkey)[idx] = z4;
        else             ((uint4*)g_dcnt)[idx - 32768] = z4;
    }

    if (bid < 32) {                         // per-block score partials
        __shared__ float red[256];
        red[tid] = __ldg(scores + bid * 256 + tid);
        __syncthreads();
        for (int o = 128; o > 0; o >>= 1) {
            if (tid < o) red[tid] += red[tid + o];
            __syncthreads();
        }
        if (tid == 0) g_part[bid] = red[0];
    } else if (bid == 32 && tid < T_TYPES) {
        float r[H_HEADS];
        #pragma unroll
        for (int h = 0; h < H_HEADS; h++) {
            float a = 0.f;
            #pragma unroll
            for (int d = 0; d < D_DIM; d++)
                a += __ldg(emb + tid * D_DIM + d) * __ldg(W + h * WSTR + 1 + d);
            r[h] = a;
        }
        g_embT[tid] = make_float4(r[0], r[1], r[2], r[3]);
    }
}

// ---------------------------------------------------------------------------
// K2: resolve all edges inline (2 edges/thread). cnt==1 → singleton.
// cnt>=2 → telescoping delta via exact hash (order-independent; ex(0)=0).
// ---------------------------------------------------------------------------
__global__ void __launch_bounds__(256) k_edges(
        const int*   __restrict__ ei,
        const float* __restrict__ scores,
        const float* __restrict__ W) {
    const int gtid = blockIdx.x * 256 + threadIdx.x;
    const int base = gtid * 2;
    const int t = base >> 17, e = base & (E_EDGES - 1);

    int2 s2 = __ldg((const int2*)(ei + (t * 2    ) * E_EDGES + e));
    int2 t2 = __ldg((const int2*)(ei + (t * 2 + 1) * E_EDGES + e));

    unsigned int key[2], f[2], w[2];
    key[0] = ((unsigned)s2.x << 13) | (unsigned)t2.x;  f[0] = field_of(key[0]);
    key[1] = ((unsigned)s2.y << 13) | (unsigned)t2.y;  f[1] = field_of(key[1]);
    w[0] = __ldg(&g_lsy[f[0] >> 3]);      // read-only in this kernel → safe
    w[1] = __ldg(&g_lsy[f[1] >> 3]);

    float4 embT = *(const float4*)&g_embT[t];   // written in K1 (prev kernel)
    float ws0 = __ldg(W + 0 * WSTR), wt0 = __ldg(W + 0 * WSTR + 33);
    float ws1 = __ldg(W + 1 * WSTR), wt1 = __ldg(W + 1 * WSTR + 33);
    float ws2 = __ldg(W + 2 * WSTR), wt2 = __ldg(W + 2 * WSTR + 33);
    float ws3 = __ldg(W + 3 * WSTR), wt3 = __ldg(W + 3 * WSTR + 33);

    #pragma unroll
    for (int k = 0; k < 2; k++) {
        unsigned int cnt = (w[k] >> ((f[k] & 7u) * 4u)) & 15u;
        unsigned int src = key[k] >> 13, tgt = key[k] & 8191u;
        float si = __ldg(scores + src);
        float sj = __ldg(scores + tgt);
        float ex0, ex1, ex2, ex3;

        if (cnt == 1u) {                    // exact singleton (~94%)
            float a0 = si * ws0 + sj * wt0 + embT.x;
            float a1 = si * ws1 + sj * wt1 + embT.y;
            float a2 = si * ws2 + sj * wt2 + embT.z;
            float a3 = si * ws3 + sj * wt3 + embT.w;
            ex0 = __expf(fmaxf(a0, NEG_SLOPE * a0)) - 1.f;
            ex1 = __expf(fmaxf(a1, NEG_SLOPE * a1)) - 1.f;
            ex2 = __expf(fmaxf(a2, NEG_SLOPE * a2)) - 1.f;
            ex3 = __expf(fmaxf(a3, NEG_SLOPE * a3)) - 1.f;
        } else {                            // dup/collision: telescoping delta
            unsigned int hh = key[k] * 0x85EBCA6Bu;
            hh = (hh ^ (hh >> 16)) & DUP_MASK;
            while (true) {
                unsigned int o = atomicCAS(&g_dkey[hh], 0u, key[k] + 1u);
                if (o == 0u || o == key[k] + 1u) break;
                hh = (hh + 1u) & DUP_MASK;
            }
            unsigned int inc   = 1u << (t * 8);
            unsigned int c_old = atomicAdd(&g_dcnt[hh], inc);
            unsigned int c_new = c_old + inc;
            float4 E0 = g_embT[0], E1 = g_embT[1], E2 = g_embT[2], E3 = g_embT[3];
            ex0 = group_ex(c_new, si, sj, ws0, wt0, E0.x, E1.x, E2.x, E3.x)
                - group_ex(c_old, si, sj, ws0, wt0, E0.x, E1.x, E2.x, E3.x);
            ex1 = group_ex(c_new, si, sj, ws1, wt1, E0.y, E1.y, E2.y, E3.y)
                - group_ex(c_old, si, sj, ws1, wt1, E0.y, E1.y, E2.y, E3.y);
            ex2 = group_ex(c_new, si, sj, ws2, wt2, E0.z, E1.z, E2.z, E3.z)
                - group_ex(c_old, si, sj, ws2, wt2, E0.z, E1.z, E2.z, E3.z);
            ex3 = group_ex(c_new, si, sj, ws3, wt3, E0.w, E1.w, E2.w, E3.w)
                - group_ex(c_old, si, sj, ws3, wt3, E0.w, E1.w, E2.w, E3.w);
        }

        float4* dst = &g_acc[src * 2];
        asm volatile("red.global.add.v4.f32 [%0], {%1,%2,%3,%4};"
                     :: "l"(dst), "f"(ex0), "f"(ex0 * sj),
                        "f"(ex1), "f"(ex1 * sj) : "memory");
        asm volatile("red.global.add.v4.f32 [%0], {%1,%2,%3,%4};"
                     :: "l"(dst + 1), "f"(ex2), "f"(ex2 * sj),
                        "f"(ex3), "f"(ex3 * sj) : "memory");
    }
}

// ---------------------------------------------------------------------------
// K3: blocks [0,32) finalize + reset g_acc; [32,160) clear lossy table.
// ---------------------------------------------------------------------------
__global__ void __launch_bounds__(256) k_final(float* __restrict__ out) {
    const int bid = blockIdx.x, tid = threadIdx.x;

    if (bid < FIN_BLOCKS) {
        float st = 0.f;
        #pragma unroll
        for (int k = 0; k < 32; k++) st += g_part[k];   // deterministic order
        int i = bid * 256 + tid;
        float4 a0 = g_acc[i * 2];
        float4 a1 = g_acc[i * 2 + 1];
        out[i] = 0.25f * ((st + a0.y) / (8192.f + a0.x)
                        + (st + a0.w) / (8192.f + a0.z)
                        + (st + a1.y) / (8192.f + a1.x)
                        + (st + a1.w) / (8192.f + a1.z));
        g_acc[i * 2]     = make_float4(0.f, 0.f, 0.f, 0.f);
        g_acc[i * 2 + 1] = make_float4(0.f, 0.f, 0.f, 0.f);
    } else {
        uint4* l4 = (uint4*)g_lsy;                       // 2^18 uint4
        uint4 z4 = make_uint4(0u, 0u, 0u, 0u);
        unsigned int b = (unsigned)(bid - FIN_BLOCKS) * 256 + tid;
        #pragma unroll
        for (int k = 0; k < 8; k++)
            l4[b + k * (CLR_L_BLOCKS * 256)] = z4;
    }
}

// ---------------------------------------------------------------------------
extern "C" void kernel_launch(void* const* d_in, const int* in_sizes, int n_in,
                              void* d_out, int out_size) {
    const float* scores = (const float*)d_in[0];   // (N, 1)
    const float* emb    = (const float*)d_in[1];   // (T, D)
    const int*   ei     = (const int*)  d_in[2];   // (T, 2, E)
    const float* W      = (const float*)d_in[3];   // (H, D+2, 1)
    float*       out    = (float*)d_out;           // (N, 1)

    k_count<<<EDGE_BLOCKS, 256>>>(ei, scores, emb, W);
    k_edges<<<EDGE_BLOCKS, 256>>>(ei, scores, W);
    k_final<<<K3_BLOCKS,   256>>>(out);
}

// round 15
// speedup vs baseline: 1.4404x; 1.0094x over previous
#include <cuda_runtime.h>

#define N_NODES   8192
#define T_TYPES   4
#define E_EDGES   131072
#define E_TOTAL   (T_TYPES * E_EDGES)   // 524288
#define H_HEADS   4
#define D_DIM     32
#define NEG_SLOPE 0.2f
#define WSTR      34                    // D_DIM + 2

// Lossy 4-bit counting table: 2^23 fields packed 8/word = 4 MiB
#define LSY_WORDS (1u << 20)
// Exact dup hash (true dups + ~6% lossy false positives, ~32K keys)
#define DUP_BITS  17
#define DUP_SIZE  (1u << DUP_BITS)
#define DUP_MASK  (DUP_SIZE - 1u)

#define EDGE_BLOCKS 512                 // 4 edges/thread (R12-proven config)
#define FIN_BLOCKS  32                  // 8192/256
#define CLR_L_BLOCKS 64
#define CLR_D_BLOCKS 32
#define K3_BLOCKS   (FIN_BLOCKS + CLR_L_BLOCKS + CLR_D_BLOCKS)  // 128

// Scratch — zero-init at module load; self-cleaned every call (K3).
__device__ unsigned int g_lsy[LSY_WORDS];
__device__ unsigned int g_dkey[DUP_SIZE];   // 0=empty else key+1
__device__ unsigned int g_dcnt[DUP_SIZE];   // packed per-type byte counts
__device__ float4 g_acc[N_NODES * 2];       // [d0,n0,d1,n1][d2,n2,d3,n3]
__device__ float4 g_embT[T_TYPES];          // embterm[t] over 4 heads
__device__ float  g_part[32];               // score partial sums

__device__ __forceinline__ unsigned int field_of(unsigned int key) {
    return (key * 0x9E3779B1u) >> 9;        // 23-bit field index
}

// PDL primitives (sm_90+): predecessor signals, dependent waits before
// consuming predecessor-written data. Graph-capturable.
__device__ __forceinline__ void pdl_trigger() {
    asm volatile("griddepcontrol.launch_dependents;" ::: "memory");
}
__device__ __forceinline__ void pdl_wait() {
    asm volatile("griddepcontrol.wait;" ::: "memory");
}

__device__ __forceinline__ float group_ex(
        unsigned int c, float si, float sj,
        float ws, float wt, float et0, float et1, float et2, float et3) {
    float c0 = (float)( c        & 0xFFu);
    float c1 = (float)((c >> 8 ) & 0xFFu);
    float c2 = (float)((c >> 16) & 0xFFu);
    float c3 = (float)((c >> 24) & 0xFFu);
    float a = (si * ws + sj * wt) * (c0 + c1 + c2 + c3)
            + c0 * et0 + c1 * et1 + c2 * et2 + c3 * et3;
    return __expf(fmaxf(a, NEG_SLOPE * a)) - 1.f;
}

// ---------------------------------------------------------------------------
// K1: lossy counting (fire-and-forget REDs) + distributed prep. No sync.
// ---------------------------------------------------------------------------
__global__ void __launch_bounds__(256) k_count(
        const int*   __restrict__ ei,
        const float* __restrict__ scores,
        const float* __restrict__ emb,
        const float* __restrict__ W) {
    const int bid = blockIdx.x, tid = threadIdx.x;
    const int gtid = bid * 256 + tid;
    const int base = gtid * 4;              // 4 contiguous edges, same type t
    const int t = base >> 17, e = base & (E_EDGES - 1);

    int4 s4 = __ldg((const int4*)(ei + (t * 2    ) * E_EDGES + e));
    int4 t4 = __ldg((const int4*)(ei + (t * 2 + 1) * E_EDGES + e));

    unsigned int f[4];
    f[0] = field_of(((unsigned)s4.x << 13) | (unsigned)t4.x);
    f[1] = field_of(((unsigned)s4.y << 13) | (unsigned)t4.y);
    f[2] = field_of(((unsigned)s4.z << 13) | (unsigned)t4.z);
    f[3] = field_of(((unsigned)s4.w << 13) | (unsigned)t4.w);

    #pragma unroll
    for (int k = 0; k < 4; k++)
        asm volatile("red.global.add.u32 [%0], %1;"
                     :: "l"(&g_lsy[f[k] >> 3]),
                        "r"(1u << ((f[k] & 7u) * 4u)) : "memory");

    if (bid < 32) {                         // per-block score partials
        __shared__ float red[256];
        red[tid] = __ldg(scores + bid * 256 + tid);
        __syncthreads();
        for (int o = 128; o > 0; o >>= 1) {
            if (tid < o) red[tid] += red[tid + o];
            __syncthreads();
        }
        if (tid == 0) g_part[bid] = red[0];
    } else if (bid == 32 && tid < T_TYPES) {
        float r[H_HEADS];
        #pragma unroll
        for (int h = 0; h < H_HEADS; h++) {
            float a = 0.f;
            #pragma unroll
            for (int d = 0; d < D_DIM; d++)
                a += __ldg(emb + tid * D_DIM + d) * __ldg(W + h * WSTR + 1 + d);
            r[h] = a;
        }
        g_embT[tid] = make_float4(r[0], r[1], r[2], r[3]);
    }

    pdl_trigger();                          // all our REDs/writes are issued
}

// ---------------------------------------------------------------------------
// K2: PDL prologue (edge loads, hashing, W loads) overlaps K1's tail; wait,
// then resolve edges inline. cnt==1 → singleton; cnt>=2 → telescoping delta.
// ---------------------------------------------------------------------------
__global__ void __launch_bounds__(256) k_edges(
        const int*   __restrict__ ei,
        const float* __restrict__ scores,
        const float* __restrict__ W) {
    const int gtid = blockIdx.x * 256 + threadIdx.x;
    const int base = gtid * 4;
    const int t = base >> 17, e = base & (E_EDGES - 1);

    // ---- prologue: independent of k_count's writes ----
    int4 s4 = __ldg((const int4*)(ei + (t * 2    ) * E_EDGES + e));
    int4 t4 = __ldg((const int4*)(ei + (t * 2 + 1) * E_EDGES + e));

    unsigned int key[4], f[4];
    key[0] = ((unsigned)s4.x << 13) | (unsigned)t4.x;  f[0] = field_of(key[0]);
    key[1] = ((unsigned)s4.y << 13) | (unsigned)t4.y;  f[1] = field_of(key[1]);
    key[2] = ((unsigned)s4.z << 13) | (unsigned)t4.z;  f[2] = field_of(key[2]);
    key[3] = ((unsigned)s4.w << 13) | (unsigned)t4.w;  f[3] = field_of(key[3]);

    float ws0 = __ldg(W + 0 * WSTR), wt0 = __ldg(W + 0 * WSTR + 33);
    float ws1 = __ldg(W + 1 * WSTR), wt1 = __ldg(W + 1 * WSTR + 33);
    float ws2 = __ldg(W + 2 * WSTR), wt2 = __ldg(W + 2 * WSTR + 33);
    float ws3 = __ldg(W + 3 * WSTR), wt3 = __ldg(W + 3 * WSTR + 33);

    // ---- wait for k_count's counts + embT to be visible ----
    pdl_wait();

    unsigned int w[4];
    #pragma unroll
    for (int k = 0; k < 4; k++)
        w[k] = __ldg(&g_lsy[f[k] >> 3]);   // read-only in this kernel → safe

    float4 embT = *(const float4*)&g_embT[t];

    #pragma unroll
    for (int k = 0; k < 4; k++) {
        unsigned int cnt = (w[k] >> ((f[k] & 7u) * 4u)) & 15u;
        unsigned int src = key[k] >> 13, tgt = key[k] & 8191u;
        float si = __ldg(scores + src);
        float sj = __ldg(scores + tgt);
        float ex0, ex1, ex2, ex3;

        if (cnt == 1u) {                    // exact singleton (~94%)
            float a0 = si * ws0 + sj * wt0 + embT.x;
            float a1 = si * ws1 + sj * wt1 + embT.y;
            float a2 = si * ws2 + sj * wt2 + embT.z;
            float a3 = si * ws3 + sj * wt3 + embT.w;
            ex0 = __expf(fmaxf(a0, NEG_SLOPE * a0)) - 1.f;
            ex1 = __expf(fmaxf(a1, NEG_SLOPE * a1)) - 1.f;
            ex2 = __expf(fmaxf(a2, NEG_SLOPE * a2)) - 1.f;
            ex3 = __expf(fmaxf(a3, NEG_SLOPE * a3)) - 1.f;
        } else {                            // dup/collision: telescoping delta
            unsigned int hh = key[k] * 0x85EBCA6Bu;
            hh = (hh ^ (hh >> 16)) & DUP_MASK;
            while (true) {
                unsigned int o = atomicCAS(&g_dkey[hh], 0u, key[k] + 1u);
                if (o == 0u || o == key[k] + 1u) break;
                hh = (hh + 1u) & DUP_MASK;
            }
            unsigned int inc   = 1u << (t * 8);
            unsigned int c_old = atomicAdd(&g_dcnt[hh], inc);
            unsigned int c_new = c_old + inc;
            float4 E0 = g_embT[0], E1 = g_embT[1], E2 = g_embT[2], E3 = g_embT[3];
            ex0 = group_ex(c_new, si, sj, ws0, wt0, E0.x, E1.x, E2.x, E3.x)
                - group_ex(c_old, si, sj, ws0, wt0, E0.x, E1.x, E2.x, E3.x);
            ex1 = group_ex(c_new, si, sj, ws1, wt1, E0.y, E1.y, E2.y, E3.y)
                - group_ex(c_old, si, sj, ws1, wt1, E0.y, E1.y, E2.y, E3.y);
            ex2 = group_ex(c_new, si, sj, ws2, wt2, E0.z, E1.z, E2.z, E3.z)
                - group_ex(c_old, si, sj, ws2, wt2, E0.z, E1.z, E2.z, E3.z);
            ex3 = group_ex(c_new, si, sj, ws3, wt3, E0.w, E1.w, E2.w, E3.w)
                - group_ex(c_old, si, sj, ws3, wt3, E0.w, E1.w, E2.w, E3.w);
        }

        float4* dst = &g_acc[src * 2];
        asm volatile("red.global.add.v4.f32 [%0], {%1,%2,%3,%4};"
                     :: "l"(dst), "f"(ex0), "f"(ex0 * sj),
                        "f"(ex1), "f"(ex1 * sj) : "memory");
        asm volatile("red.global.add.v4.f32 [%0], {%1,%2,%3,%4};"
                     :: "l"(dst + 1), "f"(ex2), "f"(ex2 * sj),
                        "f"(ex3), "f"(ex3 * sj) : "memory");
    }

    pdl_trigger();
}

// ---------------------------------------------------------------------------
// K3: waits (PDL), then: blocks [0,32) finalize + reset g_acc;
//     [32,96) clear lossy table; [96,128) clear dup hash.
// ---------------------------------------------------------------------------
__global__ void __launch_bounds__(256) k_final(float* __restrict__ out) {
    pdl_wait();                             // all k_edges REDs visible
    const int bid = blockIdx.x, tid = threadIdx.x;
    uint4 z4 = make_uint4(0u, 0u, 0u, 0u);

    if (bid < FIN_BLOCKS) {
        float st = 0.f;
        #pragma unroll
        for (int k = 0; k < 32; k++) st += g_part[k];   // deterministic order
        int i = bid * 256 + tid;
        float4 a0 = g_acc[i * 2];
        float4 a1 = g_acc[i * 2 + 1];
        out[i] = 0.25f * ((st + a0.y) / (8192.f + a0.x)
                        + (st + a0.w) / (8192.f + a0.z)
                        + (st + a1.y) / (8192.f + a1.x)
                        + (st + a1.w) / (8192.f + a1.z));
        g_acc[i * 2]     = make_float4(0.f, 0.f, 0.f, 0.f);
        g_acc[i * 2 + 1] = make_float4(0.f, 0.f, 0.f, 0.f);
    } else if (bid < FIN_BLOCKS + CLR_L_BLOCKS) {
        uint4* l4 = (uint4*)g_lsy;                       // 2^18 uint4
        unsigned int b = (unsigned)(bid - FIN_BLOCKS) * 256 + tid;
        #pragma unroll
        for (int k = 0; k < 16; k++)
            l4[b + k * (CLR_L_BLOCKS * 256)] = z4;
    } else {
        uint4* k4 = (uint4*)g_dkey;                      // 2^15 uint4
        uint4* c4 = (uint4*)g_dcnt;
        unsigned int b = (unsigned)(bid - FIN_BLOCKS - CLR_L_BLOCKS) * 256 + tid;
        #pragma unroll
        for (int k = 0; k < 4; k++) {
            k4[b + k * (CLR_D_BLOCKS * 256)] = z4;
            c4[b + k * (CLR_D_BLOCKS * 256)] = z4;
        }
    }
}

// ---------------------------------------------------------------------------
extern "C" void kernel_launch(void* const* d_in, const int* in_sizes, int n_in,
                              void* d_out, int out_size) {
    const float* scores = (const float*)d_in[0];   // (N, 1)
    const float* emb    = (const float*)d_in[1];   // (T, D)
    const int*   ei     = (const int*)  d_in[2];   // (T, 2, E)
    const float* W      = (const float*)d_in[3];   // (H, D+2, 1)
    float*       out    = (float*)d_out;           // (N, 1)

    // K1: normal launch
    k_count<<<EDGE_BLOCKS, 256>>>(ei, scores, emb, W);

    // K2, K3: programmatic dependent launches (overlap with predecessor tail)
    cudaLaunchAttribute attr[1];
    attr[0].id = cudaLaunchAttributeProgrammaticStreamSerialization;
    attr[0].val.programmaticStreamSerializationAllowed = 1;

    {
        cudaLaunchConfig_t cfg = {};
        cfg.gridDim  = dim3(EDGE_BLOCKS);
        cfg.blockDim = dim3(256);
        cfg.attrs = attr;
        cfg.numAttrs = 1;
        void* args[] = { (void*)&ei, (void*)&scores, (void*)&W };
        cudaLaunchKernelExC(&cfg, (const void*)k_edges, args);
    }
    {
        cudaLaunchConfig_t cfg = {};
        cfg.gridDim  = dim3(K3_BLOCKS);
        cfg.blockDim = dim3(256);
        cfg.attrs = attr;
        cfg.numAttrs = 1;
        void* args[] = { (void*)&out };
        cudaLaunchKernelExC(&cfg, (const void*)k_final, args);
    }
}